// round 6
// baseline (speedup 1.0000x reference)
#include <cuda_runtime.h>
#include <cstdint>
#include <cstdio>

#define D 128
#define MAXN 50000
#define LDA 132   // padded lead dim (floats) for conflict-free mma fragment loads

// Scratch (device globals: allocation-free contract). 16B-aligned for vector ld/st.
__device__ __align__(16) float g_PQR[(size_t)MAXN * 384];  // [N][384]: P=h@W1a^T, Q=h@W1b^T, R=h@U1a^T
__device__ __align__(16) float g_agg[(size_t)MAXN * D];    // scatter-add target
__device__ __align__(16) unsigned g_W2pack[2 * 16 * 32 * 16]; // per-lane tf32 B-fragments of W2
__device__ int g_oddor;                                     // OR of odd 32-bit words of edge buffer

__device__ __forceinline__ unsigned f2tf(float x){
    unsigned u; asm("cvt.rna.tf32.f32 %0, %1;" : "=r"(u) : "f"(x)); return u;
}
__device__ __forceinline__ float silu(float x){           // exact-ish (2 MUFU)
    return x * (1.0f / (1.0f + __expf(-x)));
}
__device__ __forceinline__ float silu_fast(float x){      // 1 MUFU via hw tanh
    float hx = 0.5f * x;
    float t; asm("tanh.approx.f32 %0, %1;" : "=f"(t) : "f"(hx));
    return hx + hx * t;                                   // 0.5x(1+tanh(x/2))
}
__device__ __forceinline__ void mma8(float* c, const unsigned* a, const unsigned* b){
    asm volatile(
      "mma.sync.aligned.m16n8k8.row.col.f32.tf32.tf32.f32 "
      "{%0,%1,%2,%3},{%4,%5,%6,%7},{%8,%9},{%0,%1,%2,%3};\n"
      : "+f"(c[0]), "+f"(c[1]), "+f"(c[2]), "+f"(c[3])
      : "r"(a[0]), "r"(a[1]), "r"(a[2]), "r"(a[3]), "r"(b[0]), "r"(b[1]));
}
__device__ __forceinline__ void red2(float* addr, float x, float y){
    asm volatile("red.global.add.v2.f32 [%0], {%1,%2};" :: "l"(addr), "f"(x), "f"(y) : "memory");
}

// ---------------------------------------------------------------------------
// Probe: detect edge_index element width (int64 hi-words all zero vs int32).
// ---------------------------------------------------------------------------
__global__ void probe_kernel(const int* __restrict__ ebuf)
{
    int v = 0;
    for (int i = threadIdx.x; i < 4096; i += blockDim.x)
        v |= ebuf[2 * i + 1];
    if (v) atomicOr(&g_oddor, v);
}

// ---------------------------------------------------------------------------
// Pack W2 into per-lane mma B-fragment order:
// pack[((cg*16 + ks)*32 + lane)*16 + nf*2 + r] = tf32(W2[(cg*64+nf*8+(lane>>2))*D + ks*8+(lane&3)+r*4])
// ---------------------------------------------------------------------------
__global__ void pack_kernel(const float* __restrict__ W2)
{
    int idx = blockIdx.x * 256 + threadIdx.x;
    if (idx >= 2 * 16 * 32 * 16) return;
    int j = idx & 15, lane = (idx >> 4) & 31, ks = (idx >> 9) & 15, cg = idx >> 13;
    int nf = j >> 1, r = j & 1;
    int row = cg * 64 + nf * 8 + (lane >> 2);
    int col = ks * 8 + (lane & 3) + r * 4;
    g_W2pack[idx] = f2tf(W2[row * D + col]);
}

// ---------------------------------------------------------------------------
// Kernel 1: PQR = h @ Wcat^T. 512 threads, tile 32 rows x 384 cols.
// ---------------------------------------------------------------------------
__global__ __launch_bounds__(512) void gemm1_kernel(
    const float* __restrict__ h, const float* __restrict__ W1,
    const float* __restrict__ U1, int N)
{
    extern __shared__ unsigned sm[];
    unsigned* sW = sm;               // 384*LDA
    unsigned* sA = sm + 384 * LDA;   // 32*LDA
    int tid = threadIdx.x;

    for (int idx = tid; idx < 384 * D; idx += 512) {
        int r = idx >> 7, k = idx & 127;
        float v;
        if (r < 128)      v = W1[r * 257 + k];
        else if (r < 256) v = W1[(r - 128) * 257 + 128 + k];
        else              v = U1[(r - 256) * 256 + k];
        sW[r * LDA + k] = f2tf(v);
    }

    int w = tid >> 5, l = tid & 31, g = l >> 2, t4 = l & 3;
    int nbase = w * 24;
    int ntiles = (N + 31) >> 5;

    for (int tt = blockIdx.x; tt < ntiles; tt += gridDim.x) {
        __syncthreads();
        int row0 = tt << 5;
        #pragma unroll
        for (int it = 0; it < 2; ++it) {
            int idx = tid + it * 512;
            int r = idx >> 5, q = idx & 31;
            int i = row0 + r;
            float4 v = make_float4(0.f, 0.f, 0.f, 0.f);
            if (i < N) v = *(const float4*)&h[(size_t)i * D + q * 4];
            uint4 u = make_uint4(f2tf(v.x), f2tf(v.y), f2tf(v.z), f2tf(v.w));
            *(uint4*)&sA[r * LDA + q * 4] = u;
        }
        __syncthreads();

        float acc[2][3][4];
        #pragma unroll
        for (int mf = 0; mf < 2; mf++)
            #pragma unroll
            for (int nf = 0; nf < 3; nf++)
                #pragma unroll
                for (int q = 0; q < 4; q++) acc[mf][nf][q] = 0.f;

        #pragma unroll
        for (int ks = 0; ks < 16; ++ks) {
            int kb = ks * 8;
            unsigned a[2][4];
            #pragma unroll
            for (int mf = 0; mf < 2; mf++) {
                int r0 = mf * 16 + g;
                a[mf][0] = sA[r0 * LDA + kb + t4];
                a[mf][1] = sA[(r0 + 8) * LDA + kb + t4];
                a[mf][2] = sA[r0 * LDA + kb + t4 + 4];
                a[mf][3] = sA[(r0 + 8) * LDA + kb + t4 + 4];
            }
            #pragma unroll
            for (int nf = 0; nf < 3; nf++) {
                unsigned b[2];
                int n = nbase + nf * 8 + g;
                b[0] = sW[n * LDA + kb + t4];
                b[1] = sW[n * LDA + kb + t4 + 4];
                mma8(acc[0][nf], a[0], b);
                mma8(acc[1][nf], a[1], b);
            }
        }
        #pragma unroll
        for (int mf = 0; mf < 2; mf++) {
            int i0 = row0 + mf * 16 + g;
            int i1 = i0 + 8;
            #pragma unroll
            for (int nf = 0; nf < 3; nf++) {
                int col = nbase + nf * 8 + t4 * 2;
                if (i0 < N) *(float2*)&g_PQR[(size_t)i0 * 384 + col] = make_float2(acc[mf][nf][0], acc[mf][nf][1]);
                if (i1 < N) *(float2*)&g_PQR[(size_t)i1 * 384 + col] = make_float2(acc[mf][nf][2], acc[mf][nf][3]);
            }
        }
    }
}

// ---------------------------------------------------------------------------
// Kernel 2: edge kernel. Tile = 64 edges, 256 threads, 3 CTAs/SM.
// W2 B-fragments from L1-resident g_W2pack (LDG.128); only sT in smem.
// ---------------------------------------------------------------------------
__global__ __launch_bounds__(256, 3) void edge_kernel(
    const float* __restrict__ coords, const void* __restrict__ eraw,
    const float* __restrict__ W1, const float* __restrict__ b1,
    const float* __restrict__ b2, int N, int E)
{
    extern __shared__ unsigned sm[];
    unsigned* sT  = sm;              // 64*LDA (t tile, then m tile)
    float* sb1   = (float*)(sT + 64 * LDA);
    float* sb2   = sb1 + 128;
    float* swc   = sb2 + 128;
    float* sDist = swc + 128;
    int*   sS    = (int*)(sDist + 64);
    int*   sR    = sS + 64;
    int tid = threadIdx.x;

    const bool is64 = (g_oddor == 0);
    const int*       e32 = (const int*)eraw;
    const long long* e64 = (const long long*)eraw;

    if (tid < 128) { sb1[tid] = b1[tid]; sb2[tid] = b2[tid]; swc[tid] = W1[tid * 257 + 256]; }

    int w = tid >> 5, l = tid & 31, g = l >> 2, t4 = l & 3;
    int wr = w >> 1, wc = w & 1;
    int ntiles = (E + 63) >> 6;

    for (int tt = blockIdx.x; tt < ntiles; tt += gridDim.x) {
        __syncthreads();
        int e0 = tt << 6;
        if (tid < 64) {
            int e = e0 + tid;
            int s = 0, r = 0; float dd = 0.f;
            if (e < E) {
                if (is64) { s = (int)e64[e]; r = (int)e64[(size_t)E + e]; }
                else      { s = e32[e];      r = e32[(size_t)E + e]; }
                if ((unsigned)s >= (unsigned)N) s = 0;
                if ((unsigned)r >= (unsigned)N) r = 0;
                float dx = coords[s * 3 + 0] - coords[r * 3 + 0];
                float dy = coords[s * 3 + 1] - coords[r * 3 + 1];
                float dz = coords[s * 3 + 2] - coords[r * 3 + 2];
                dd = sqrtf(dx * dx + dy * dy + dz * dz);
            }
            sS[tid] = s; sR[tid] = r; sDist[tid] = dd;
        }
        __syncthreads();

        // build t tile: 2048 float4-quads
        #pragma unroll
        for (int half = 0; half < 2; ++half) {
            float4 pv[4], qv[4]; float dv[4]; int el[4], ocl[4];
            #pragma unroll
            for (int it = 0; it < 4; ++it) {
                int idx = tid + (half * 4 + it) * 256;
                int e = idx >> 5, oc = idx & 31;
                el[it] = e; ocl[it] = oc;
                int s = sS[e], r = sR[e];
                pv[it] = *(const float4*)&g_PQR[(size_t)s * 384 + oc * 4];
                qv[it] = *(const float4*)&g_PQR[(size_t)r * 384 + 128 + oc * 4];
                dv[it] = sDist[e];
            }
            #pragma unroll
            for (int it = 0; it < 4; ++it) {
                int e = el[it], c = ocl[it] * 4;
                float x0 = pv[it].x + qv[it].x + dv[it] * swc[c + 0] + sb1[c + 0];
                float x1 = pv[it].y + qv[it].y + dv[it] * swc[c + 1] + sb1[c + 1];
                float x2 = pv[it].z + qv[it].z + dv[it] * swc[c + 2] + sb1[c + 2];
                float x3 = pv[it].w + qv[it].w + dv[it] * swc[c + 3] + sb1[c + 3];
                uint4 st = make_uint4(f2tf(silu_fast(x0)), f2tf(silu_fast(x1)),
                                      f2tf(silu_fast(x2)), f2tf(silu_fast(x3)));
                *(uint4*)&sT[e * LDA + c] = st;
            }
        }
        __syncthreads();

        float acc[8][4];
        #pragma unroll
        for (int nf = 0; nf < 8; nf++)
            #pragma unroll
            for (int q = 0; q < 4; q++) acc[nf][q] = 0.f;

        const uint4* __restrict__ pkbase =
            (const uint4*)&g_W2pack[((size_t)wc * 16 * 32 + l) * 16];

        #pragma unroll
        for (int ks = 0; ks < 16; ++ks) {
            int kb = ks * 8;
            unsigned a[4];
            int r0 = wr * 16 + g;
            a[0] = sT[r0 * LDA + kb + t4];
            a[1] = sT[(r0 + 8) * LDA + kb + t4];
            a[2] = sT[r0 * LDA + kb + t4 + 4];
            a[3] = sT[(r0 + 8) * LDA + kb + t4 + 4];
            // 4x LDG.128, L1-resident, coalesced: 16 B-fragment words
            const uint4* pk = pkbase + (size_t)ks * 32 * 4;  // (ks*32 lanes)*16 words / 4
            uint4 q0 = pk[0], q1 = pk[1], q2 = pk[2], q3 = pk[3];
            unsigned bb[16] = { q0.x,q0.y,q0.z,q0.w, q1.x,q1.y,q1.z,q1.w,
                                q2.x,q2.y,q2.z,q2.w, q3.x,q3.y,q3.z,q3.w };
            #pragma unroll
            for (int nf = 0; nf < 8; nf++)
                mma8(acc[nf], a, &bb[nf * 2]);
        }
        __syncthreads();   // all mma reads of sT done before m overwrite

        // write m tile into sT
        int rA = wr * 16 + g;
        #pragma unroll
        for (int nf = 0; nf < 8; nf++) {
            int col = wc * 64 + nf * 8 + t4 * 2;
            sT[rA * LDA + col]           = __float_as_uint(silu_fast(acc[nf][0] + sb2[col]));
            sT[rA * LDA + col + 1]       = __float_as_uint(silu_fast(acc[nf][1] + sb2[col + 1]));
            sT[(rA + 8) * LDA + col]     = __float_as_uint(silu_fast(acc[nf][2] + sb2[col]));
            sT[(rA + 8) * LDA + col + 1] = __float_as_uint(silu_fast(acc[nf][3] + sb2[col + 1]));
        }
        __syncthreads();

        // scatter: each warp handles one row per j; 32 lanes cover the 512B row
        #pragma unroll
        for (int j = 0; j < 8; ++j) {
            int e = w + j * 8;
            if (e0 + e < E) {
                float4 v = *(const float4*)&sT[e * LDA + l * 4];
                float* dst = &g_agg[(size_t)sR[e] * D + l * 4];
                red2(dst, v.x, v.y);
                red2(dst + 2, v.z, v.w);
            }
        }
    }
}

// ---------------------------------------------------------------------------
// Kernel 3: node update. 512 threads, tile 128 nodes. Exact silu (protect accuracy).
// ---------------------------------------------------------------------------
__global__ __launch_bounds__(512) void node_kernel(
    const float* __restrict__ h, const float* __restrict__ U1,
    const float* __restrict__ U2, const float* __restrict__ c1,
    const float* __restrict__ c2, float* __restrict__ out, int N)
{
    extern __shared__ unsigned sm[];
    unsigned* sW = sm;               // 256*LDA (U1b rows 0..127, U2 rows 128..255)
    unsigned* sA = sm + 256 * LDA;   // 128*LDA (agg tile, then t tile)
    float* sc1 = (float*)(sA + 128 * LDA);
    float* sc2 = sc1 + 128;
    int tid = threadIdx.x;

    #pragma unroll
    for (int it = 0; it < 16; ++it) {
        int idx = tid + it * 512;
        int r = idx >> 5, q = idx & 31;
        float4 v;
        if (r < 128) v = *(const float4*)&U1[r * 256 + 128 + q * 4];
        else         v = *(const float4*)&U2[(r - 128) * D + q * 4];
        uint4 u = make_uint4(f2tf(v.x), f2tf(v.y), f2tf(v.z), f2tf(v.w));
        *(uint4*)&sW[r * LDA + q * 4] = u;
    }
    if (tid < 128) { sc1[tid] = c1[tid]; sc2[tid] = c2[tid]; }

    int w = tid >> 5, l = tid & 31, g = l >> 2, t4 = l & 3;
    int wr = w >> 1, wc = w & 1;
    int ntiles = (N + 127) >> 7;

    for (int tt = blockIdx.x; tt < ntiles; tt += gridDim.x) {
        __syncthreads();
        int n0 = tt << 7;
        #pragma unroll
        for (int it = 0; it < 8; ++it) {
            int idx = tid + it * 512;
            int r = idx >> 5, q = idx & 31;
            int i = n0 + r;
            float4 v = make_float4(0.f, 0.f, 0.f, 0.f);
            if (i < N) v = *(const float4*)&g_agg[(size_t)i * D + q * 4];
            uint4 u = make_uint4(f2tf(v.x), f2tf(v.y), f2tf(v.z), f2tf(v.w));
            *(uint4*)&sA[r * LDA + q * 4] = u;
        }
        __syncthreads();

        float acc[8][4];
        #pragma unroll
        for (int nf = 0; nf < 8; nf++)
            #pragma unroll
            for (int q = 0; q < 4; q++) acc[nf][q] = 0.f;

        #pragma unroll
        for (int ks = 0; ks < 16; ++ks) {
            int kb = ks * 8;
            unsigned a[4];
            int r0 = wr * 16 + g;
            a[0] = sA[r0 * LDA + kb + t4];
            a[1] = sA[(r0 + 8) * LDA + kb + t4];
            a[2] = sA[r0 * LDA + kb + t4 + 4];
            a[3] = sA[(r0 + 8) * LDA + kb + t4 + 4];
            #pragma unroll
            for (int nf = 0; nf < 8; nf++) {
                unsigned b[2];
                int n = wc * 64 + nf * 8 + g;
                b[0] = sW[n * LDA + kb + t4];
                b[1] = sW[n * LDA + kb + t4 + 4];
                mma8(acc[nf], a, b);
            }
        }
        __syncthreads();  // all warps done reading agg tile before overwrite with t

        int rA = wr * 16 + g;
        int i0 = n0 + rA, i1 = i0 + 8;
        #pragma unroll
        for (int nf = 0; nf < 8; nf++) {
            int col = wc * 64 + nf * 8 + t4 * 2;
            float r00 = 0.f, r01 = 0.f, r10 = 0.f, r11 = 0.f;
            if (i0 < N) { float2 rv = *(const float2*)&g_PQR[(size_t)i0 * 384 + 256 + col]; r00 = rv.x; r01 = rv.y; }
            if (i1 < N) { float2 rv = *(const float2*)&g_PQR[(size_t)i1 * 384 + 256 + col]; r10 = rv.x; r11 = rv.y; }
            sA[rA * LDA + col]           = f2tf(silu(acc[nf][0] + r00 + sc1[col]));
            sA[rA * LDA + col + 1]       = f2tf(silu(acc[nf][1] + r01 + sc1[col + 1]));
            sA[(rA + 8) * LDA + col]     = f2tf(silu(acc[nf][2] + r10 + sc1[col]));
            sA[(rA + 8) * LDA + col + 1] = f2tf(silu(acc[nf][3] + r11 + sc1[col + 1]));
        }
        __syncthreads();

        float acc2[8][4];
        #pragma unroll
        for (int nf = 0; nf < 8; nf++)
            #pragma unroll
            for (int q = 0; q < 4; q++) acc2[nf][q] = 0.f;

        #pragma unroll
        for (int ks = 0; ks < 16; ++ks) {
            int kb = ks * 8;
            unsigned a[4];
            int r0 = wr * 16 + g;
            a[0] = sA[r0 * LDA + kb + t4];
            a[1] = sA[(r0 + 8) * LDA + kb + t4];
            a[2] = sA[r0 * LDA + kb + t4 + 4];
            a[3] = sA[(r0 + 8) * LDA + kb + t4 + 4];
            #pragma unroll
            for (int nf = 0; nf < 8; nf++) {
                unsigned b[2];
                int n = 128 + wc * 64 + nf * 8 + g;
                b[0] = sW[n * LDA + kb + t4];
                b[1] = sW[n * LDA + kb + t4 + 4];
                mma8(acc2[nf], a, b);
            }
        }

        #pragma unroll
        for (int nf = 0; nf < 8; nf++) {
            int col = wc * 64 + nf * 8 + t4 * 2;
            if (i0 < N) {
                float2 hv = *(const float2*)&h[(size_t)i0 * D + col];
                *(float2*)&out[(size_t)i0 * D + col] =
                    make_float2(hv.x + acc2[nf][0] + sc2[col], hv.y + acc2[nf][1] + sc2[col + 1]);
            }
            if (i1 < N) {
                float2 hv = *(const float2*)&h[(size_t)i1 * D + col];
                *(float2*)&out[(size_t)i1 * D + col] =
                    make_float2(hv.x + acc2[nf][2] + sc2[col], hv.y + acc2[nf][3] + sc2[col + 1]);
            }
        }
    }
}

// ---------------------------------------------------------------------------
extern "C" void kernel_launch(void* const* d_in, const int* in_sizes, int n_in,
                              void* d_out, int out_size)
{
    const float* h      = (const float*)d_in[0];
    const float* coords = (const float*)d_in[1];
    const void*  eraw   = (const void*)d_in[2];
    const float* W1     = (const float*)d_in[3];
    const float* b1     = (const float*)d_in[4];
    const float* W2     = (const float*)d_in[5];
    const float* b2     = (const float*)d_in[6];
    const float* U1     = (const float*)d_in[7];
    const float* c1     = (const float*)d_in[8];
    const float* U2     = (const float*)d_in[9];
    const float* c2     = (const float*)d_in[10];

    int N = in_sizes[0] / D;
    int E = in_sizes[2] / 2;
    if (N > MAXN) N = MAXN;

    const int SMEM1 = (384 * LDA + 32 * LDA) * 4;                       // 219,648
    const int SMEM2 = 64 * LDA * 4 + (3 * 128 + 64) * 4 + 2 * 64 * 4;   // 36,096
    const int SMEM3 = (256 * LDA + 128 * LDA) * 4 + 2 * 128 * 4;        // 203,776

    cudaFuncSetAttribute(gemm1_kernel, cudaFuncAttributeMaxDynamicSharedMemorySize, SMEM1);
    cudaFuncSetAttribute(edge_kernel,  cudaFuncAttributeMaxDynamicSharedMemorySize, SMEM2);
    cudaFuncSetAttribute(node_kernel,  cudaFuncAttributeMaxDynamicSharedMemorySize, SMEM3);

    void* aggPtr = nullptr;
    cudaGetSymbolAddress(&aggPtr, g_agg);
    cudaMemsetAsync(aggPtr, 0, (size_t)N * D * sizeof(float));
    void* flagPtr = nullptr;
    cudaGetSymbolAddress(&flagPtr, g_oddor);
    cudaMemsetAsync(flagPtr, 0, sizeof(int));

    probe_kernel<<<1, 256>>>((const int*)eraw);
    pack_kernel<<<64, 256>>>(W2);
    gemm1_kernel<<<152, 512, SMEM1>>>(h, W1, U1, N);
    edge_kernel<<<444, 256, SMEM2>>>(coords, eraw, W1, b1, b2, N, E);
    node_kernel<<<152, 512, SMEM3>>>(h, U1, U2, c1, c2, (float*)d_out, N);
}

// round 7
// speedup vs baseline: 1.5025x; 1.5025x over previous
#include <cuda_runtime.h>
#include <cstdint>
#include <cstdio>

#define D 128
#define MAXN 50000
#define LDA 132   // padded lead dim (floats) for conflict-free mma fragment loads

// Scratch (device globals: allocation-free contract). 16B-aligned for vector ld/st.
__device__ __align__(16) float g_PQR[(size_t)MAXN * 384];  // [N][384]: P=h@W1a^T, Q=h@W1b^T, R=h@U1a^T
__device__ __align__(16) float g_agg[(size_t)MAXN * D];    // scatter-add target
__device__ int g_oddor;                                     // OR of odd 32-bit words of edge buffer

__device__ __forceinline__ unsigned f2tf(float x){
    unsigned u; asm("cvt.rna.tf32.f32 %0, %1;" : "=r"(u) : "f"(x)); return u;
}
__device__ __forceinline__ float silu(float x){           // exact-ish (2 MUFU)
    return x * (1.0f / (1.0f + __expf(-x)));
}
__device__ __forceinline__ float silu_fast(float x){      // 1 MUFU via hw tanh
    float hx = 0.5f * x;
    float t; asm("tanh.approx.f32 %0, %1;" : "=f"(t) : "f"(hx));
    return hx + hx * t;                                   // 0.5x(1+tanh(x/2))
}
__device__ __forceinline__ void mma8(float* c, const unsigned* a, const unsigned* b){
    asm volatile(
      "mma.sync.aligned.m16n8k8.row.col.f32.tf32.tf32.f32 "
      "{%0,%1,%2,%3},{%4,%5,%6,%7},{%8,%9},{%0,%1,%2,%3};\n"
      : "+f"(c[0]), "+f"(c[1]), "+f"(c[2]), "+f"(c[3])
      : "r"(a[0]), "r"(a[1]), "r"(a[2]), "r"(a[3]), "r"(b[0]), "r"(b[1]));
}
__device__ __forceinline__ void red2(float* addr, float x, float y){
    asm volatile("red.global.add.v2.f32 [%0], {%1,%2};" :: "l"(addr), "f"(x), "f"(y) : "memory");
}

// ---------------------------------------------------------------------------
// Probe: detect edge_index element width (int64 hi-words all zero vs int32).
// ---------------------------------------------------------------------------
__global__ void probe_kernel(const int* __restrict__ ebuf)
{
    int v = 0;
    for (int i = threadIdx.x; i < 4096; i += blockDim.x)
        v |= ebuf[2 * i + 1];
    if (v) atomicOr(&g_oddor, v);
}

// ---------------------------------------------------------------------------
// Kernel 1: PQR = h @ Wcat^T. 512 threads, tile 32 rows x 384 cols.
// ---------------------------------------------------------------------------
__global__ __launch_bounds__(512) void gemm1_kernel(
    const float* __restrict__ h, const float* __restrict__ W1,
    const float* __restrict__ U1, int N)
{
    extern __shared__ unsigned sm[];
    unsigned* sW = sm;               // 384*LDA
    unsigned* sA = sm + 384 * LDA;   // 32*LDA
    int tid = threadIdx.x;

    for (int idx = tid; idx < 384 * D; idx += 512) {
        int r = idx >> 7, k = idx & 127;
        float v;
        if (r < 128)      v = W1[r * 257 + k];
        else if (r < 256) v = W1[(r - 128) * 257 + 128 + k];
        else              v = U1[(r - 256) * 256 + k];
        sW[r * LDA + k] = f2tf(v);
    }

    int w = tid >> 5, l = tid & 31, g = l >> 2, t4 = l & 3;
    int nbase = w * 24;
    int ntiles = (N + 31) >> 5;

    for (int tt = blockIdx.x; tt < ntiles; tt += gridDim.x) {
        __syncthreads();
        int row0 = tt << 5;
        #pragma unroll
        for (int it = 0; it < 2; ++it) {
            int idx = tid + it * 512;
            int r = idx >> 5, q = idx & 31;
            int i = row0 + r;
            float4 v = make_float4(0.f, 0.f, 0.f, 0.f);
            if (i < N) v = *(const float4*)&h[(size_t)i * D + q * 4];
            uint4 u = make_uint4(f2tf(v.x), f2tf(v.y), f2tf(v.z), f2tf(v.w));
            *(uint4*)&sA[r * LDA + q * 4] = u;
        }
        __syncthreads();

        float acc[2][3][4];
        #pragma unroll
        for (int mf = 0; mf < 2; mf++)
            #pragma unroll
            for (int nf = 0; nf < 3; nf++)
                #pragma unroll
                for (int q = 0; q < 4; q++) acc[mf][nf][q] = 0.f;

        #pragma unroll
        for (int ks = 0; ks < 16; ++ks) {
            int kb = ks * 8;
            unsigned a[2][4];
            #pragma unroll
            for (int mf = 0; mf < 2; mf++) {
                int r0 = mf * 16 + g;
                a[mf][0] = sA[r0 * LDA + kb + t4];
                a[mf][1] = sA[(r0 + 8) * LDA + kb + t4];
                a[mf][2] = sA[r0 * LDA + kb + t4 + 4];
                a[mf][3] = sA[(r0 + 8) * LDA + kb + t4 + 4];
            }
            #pragma unroll
            for (int nf = 0; nf < 3; nf++) {
                unsigned b[2];
                int n = nbase + nf * 8 + g;
                b[0] = sW[n * LDA + kb + t4];
                b[1] = sW[n * LDA + kb + t4 + 4];
                mma8(acc[0][nf], a[0], b);
                mma8(acc[1][nf], a[1], b);
            }
        }
        #pragma unroll
        for (int mf = 0; mf < 2; mf++) {
            int i0 = row0 + mf * 16 + g;
            int i1 = i0 + 8;
            #pragma unroll
            for (int nf = 0; nf < 3; nf++) {
                int col = nbase + nf * 8 + t4 * 2;
                if (i0 < N) *(float2*)&g_PQR[(size_t)i0 * 384 + col] = make_float2(acc[mf][nf][0], acc[mf][nf][1]);
                if (i1 < N) *(float2*)&g_PQR[(size_t)i1 * 384 + col] = make_float2(acc[mf][nf][2], acc[mf][nf][3]);
            }
        }
    }
}

// ---------------------------------------------------------------------------
// Kernel 2: edge kernel v3. Tile = 64 edges, 256 threads, 2 CTAs/SM.
// W2 in smem. Warp-uniform shfl index loads (no index smem phase).
// mf=2 x nf=4 blocking: each warp 32 rows x 32 cols. 2 syncs/tile.
// Scatter directly from accumulator registers (bias+silu+red.v2).
// ---------------------------------------------------------------------------
__global__ __launch_bounds__(256, 2) void edge_kernel(
    const float* __restrict__ coords, const void* __restrict__ eraw,
    const float* __restrict__ W1, const float* __restrict__ b1,
    const float* __restrict__ W2, const float* __restrict__ b2,
    int N, int E)
{
    extern __shared__ unsigned sm[];
    unsigned* sW2 = sm;               // 128*LDA
    unsigned* sT  = sm + 128 * LDA;   // 64*LDA (t tile)
    float* sb1   = (float*)(sT + 64 * LDA);
    float* sb2   = sb1 + 128;
    float* swc   = sb2 + 128;
    int tid = threadIdx.x;

    const bool is64 = (g_oddor == 0);
    const int*       e32 = (const int*)eraw;
    const long long* e64 = (const long long*)eraw;

    // vectorized W2 -> smem (tf32)
    #pragma unroll
    for (int it = 0; it < 16; ++it) {
        int idx = tid + it * 256;
        int o = idx >> 5, q = idx & 31;
        float4 v = *(const float4*)&W2[o * D + q * 4];
        uint4 u = make_uint4(f2tf(v.x), f2tf(v.y), f2tf(v.z), f2tf(v.w));
        *(uint4*)&sW2[o * LDA + q * 4] = u;
    }
    if (tid < 128) { sb1[tid] = b1[tid]; sb2[tid] = b2[tid]; swc[tid] = W1[tid * 257 + 256]; }
    __syncthreads();

    int w = tid >> 5, l = tid & 31, g = l >> 2, t4 = l & 3;
    int wr = w & 1, wcc = w >> 1;     // 2 row-groups x 4 col-groups
    int ntiles = (E + 63) >> 6;

    for (int tt = blockIdx.x; tt < ntiles; tt += gridDim.x) {
        int e0 = tt << 6;

        // ---- build t tile: each warp covers edges w, w+8, ..., w+56 ----
        #pragma unroll
        for (int half = 0; half < 2; ++half) {
            float4 pv[4], qv[4]; float dv[4]; int el[4];
            #pragma unroll
            for (int it = 0; it < 4; ++it) {
                int e_loc = w + (half * 4 + it) * 8;
                el[it] = e_loc;
                int e = e0 + e_loc;
                int v = 0;
                if (l < 2 && e < E)
                    v = is64 ? (int)e64[(size_t)l * E + e] : e32[(size_t)l * E + e];
                int s = __shfl_sync(0xffffffffu, v, 0);
                int r = __shfl_sync(0xffffffffu, v, 1);
                if ((unsigned)s >= (unsigned)N) s = 0;
                if ((unsigned)r >= (unsigned)N) r = 0;
                float cd = 0.f;
                if (l < 3) cd = coords[s * 3 + l] - coords[r * 3 + l];
                float dx = __shfl_sync(0xffffffffu, cd, 0);
                float dy = __shfl_sync(0xffffffffu, cd, 1);
                float dz = __shfl_sync(0xffffffffu, cd, 2);
                dv[it] = sqrtf(dx * dx + dy * dy + dz * dz);
                pv[it] = *(const float4*)&g_PQR[(size_t)s * 384 + l * 4];
                qv[it] = *(const float4*)&g_PQR[(size_t)r * 384 + 128 + l * 4];
            }
            #pragma unroll
            for (int it = 0; it < 4; ++it) {
                int c = l * 4;
                float x0 = pv[it].x + qv[it].x + dv[it] * swc[c + 0] + sb1[c + 0];
                float x1 = pv[it].y + qv[it].y + dv[it] * swc[c + 1] + sb1[c + 1];
                float x2 = pv[it].z + qv[it].z + dv[it] * swc[c + 2] + sb1[c + 2];
                float x3 = pv[it].w + qv[it].w + dv[it] * swc[c + 3] + sb1[c + 3];
                uint4 st = make_uint4(f2tf(silu_fast(x0)), f2tf(silu_fast(x1)),
                                      f2tf(silu_fast(x2)), f2tf(silu_fast(x3)));
                *(uint4*)&sT[el[it] * LDA + c] = st;
            }
        }
        __syncthreads();

        // ---- GEMM2: warp computes 32 rows (wr) x 32 cols (wcc) ----
        float acc[2][4][4];
        #pragma unroll
        for (int mf = 0; mf < 2; mf++)
            #pragma unroll
            for (int nf = 0; nf < 4; nf++)
                #pragma unroll
                for (int q = 0; q < 4; q++) acc[mf][nf][q] = 0.f;

        #pragma unroll
        for (int ks = 0; ks < 16; ++ks) {
            int kb = ks * 8;
            unsigned a[2][4];
            #pragma unroll
            for (int mf = 0; mf < 2; mf++) {
                int r0 = wr * 32 + mf * 16 + g;
                a[mf][0] = sT[r0 * LDA + kb + t4];
                a[mf][1] = sT[(r0 + 8) * LDA + kb + t4];
                a[mf][2] = sT[r0 * LDA + kb + t4 + 4];
                a[mf][3] = sT[(r0 + 8) * LDA + kb + t4 + 4];
            }
            #pragma unroll
            for (int nf = 0; nf < 4; nf++) {
                unsigned b[2];
                int n = wcc * 32 + nf * 8 + g;
                b[0] = sW2[n * LDA + kb + t4];
                b[1] = sW2[n * LDA + kb + t4 + 4];
                mma8(acc[0][nf], a[0], b);
                mma8(acc[1][nf], a[1], b);
            }
        }
        __syncthreads();   // sT free for next tile's t-build

        // ---- scatter straight from regs: bias + silu + red.v2 ----
        int rowlane = wr * 32 + l;     // this warp's 32 tile-rows
        int vrec = 0;
        if (e0 + rowlane < E)
            vrec = is64 ? (int)e64[(size_t)E + e0 + rowlane] : e32[(size_t)E + e0 + rowlane];
        if ((unsigned)vrec >= (unsigned)N) vrec = 0;

        #pragma unroll
        for (int mf = 0; mf < 2; mf++) {
            #pragma unroll
            for (int hh = 0; hh < 2; ++hh) {
                int rsel = mf * 16 + hh * 8 + g;
                int rec = __shfl_sync(0xffffffffu, vrec, rsel);
                bool valid = (e0 + wr * 32 + rsel) < E;
                if (valid) {
                    #pragma unroll
                    for (int nf = 0; nf < 4; nf++) {
                        int col = wcc * 32 + nf * 8 + t4 * 2;
                        float m0 = silu_fast(acc[mf][nf][hh * 2]     + sb2[col]);
                        float m1 = silu_fast(acc[mf][nf][hh * 2 + 1] + sb2[col + 1]);
                        red2(&g_agg[(size_t)rec * D + col], m0, m1);
                    }
                }
            }
        }
    }
}

// ---------------------------------------------------------------------------
// Kernel 3: node update. 512 threads, tile 128 nodes. Exact silu (protect accuracy).
// ---------------------------------------------------------------------------
__global__ __launch_bounds__(512) void node_kernel(
    const float* __restrict__ h, const float* __restrict__ U1,
    const float* __restrict__ U2, const float* __restrict__ c1,
    const float* __restrict__ c2, float* __restrict__ out, int N)
{
    extern __shared__ unsigned sm[];
    unsigned* sW = sm;               // 256*LDA (U1b rows 0..127, U2 rows 128..255)
    unsigned* sA = sm + 256 * LDA;   // 128*LDA (agg tile, then t tile)
    float* sc1 = (float*)(sA + 128 * LDA);
    float* sc2 = sc1 + 128;
    int tid = threadIdx.x;

    #pragma unroll
    for (int it = 0; it < 16; ++it) {
        int idx = tid + it * 512;
        int r = idx >> 5, q = idx & 31;
        float4 v;
        if (r < 128) v = *(const float4*)&U1[r * 256 + 128 + q * 4];
        else         v = *(const float4*)&U2[(r - 128) * D + q * 4];
        uint4 u = make_uint4(f2tf(v.x), f2tf(v.y), f2tf(v.z), f2tf(v.w));
        *(uint4*)&sW[r * LDA + q * 4] = u;
    }
    if (tid < 128) { sc1[tid] = c1[tid]; sc2[tid] = c2[tid]; }

    int w = tid >> 5, l = tid & 31, g = l >> 2, t4 = l & 3;
    int wr = w >> 1, wc = w & 1;
    int ntiles = (N + 127) >> 7;

    for (int tt = blockIdx.x; tt < ntiles; tt += gridDim.x) {
        __syncthreads();
        int n0 = tt << 7;
        #pragma unroll
        for (int it = 0; it < 8; ++it) {
            int idx = tid + it * 512;
            int r = idx >> 5, q = idx & 31;
            int i = n0 + r;
            float4 v = make_float4(0.f, 0.f, 0.f, 0.f);
            if (i < N) v = *(const float4*)&g_agg[(size_t)i * D + q * 4];
            uint4 u = make_uint4(f2tf(v.x), f2tf(v.y), f2tf(v.z), f2tf(v.w));
            *(uint4*)&sA[r * LDA + q * 4] = u;
        }
        __syncthreads();

        float acc[8][4];
        #pragma unroll
        for (int nf = 0; nf < 8; nf++)
            #pragma unroll
            for (int q = 0; q < 4; q++) acc[nf][q] = 0.f;

        #pragma unroll
        for (int ks = 0; ks < 16; ++ks) {
            int kb = ks * 8;
            unsigned a[4];
            int r0 = wr * 16 + g;
            a[0] = sA[r0 * LDA + kb + t4];
            a[1] = sA[(r0 + 8) * LDA + kb + t4];
            a[2] = sA[r0 * LDA + kb + t4 + 4];
            a[3] = sA[(r0 + 8) * LDA + kb + t4 + 4];
            #pragma unroll
            for (int nf = 0; nf < 8; nf++) {
                unsigned b[2];
                int n = wc * 64 + nf * 8 + g;
                b[0] = sW[n * LDA + kb + t4];
                b[1] = sW[n * LDA + kb + t4 + 4];
                mma8(acc[nf], a, b);
            }
        }
        __syncthreads();  // all warps done reading agg tile before overwrite with t

        int rA = wr * 16 + g;
        int i0 = n0 + rA, i1 = i0 + 8;
        #pragma unroll
        for (int nf = 0; nf < 8; nf++) {
            int col = wc * 64 + nf * 8 + t4 * 2;
            float r00 = 0.f, r01 = 0.f, r10 = 0.f, r11 = 0.f;
            if (i0 < N) { float2 rv = *(const float2*)&g_PQR[(size_t)i0 * 384 + 256 + col]; r00 = rv.x; r01 = rv.y; }
            if (i1 < N) { float2 rv = *(const float2*)&g_PQR[(size_t)i1 * 384 + 256 + col]; r10 = rv.x; r11 = rv.y; }
            sA[rA * LDA + col]           = f2tf(silu(acc[nf][0] + r00 + sc1[col]));
            sA[rA * LDA + col + 1]       = f2tf(silu(acc[nf][1] + r01 + sc1[col + 1]));
            sA[(rA + 8) * LDA + col]     = f2tf(silu(acc[nf][2] + r10 + sc1[col]));
            sA[(rA + 8) * LDA + col + 1] = f2tf(silu(acc[nf][3] + r11 + sc1[col + 1]));
        }
        __syncthreads();

        float acc2[8][4];
        #pragma unroll
        for (int nf = 0; nf < 8; nf++)
            #pragma unroll
            for (int q = 0; q < 4; q++) acc2[nf][q] = 0.f;

        #pragma unroll
        for (int ks = 0; ks < 16; ++ks) {
            int kb = ks * 8;
            unsigned a[4];
            int r0 = wr * 16 + g;
            a[0] = sA[r0 * LDA + kb + t4];
            a[1] = sA[(r0 + 8) * LDA + kb + t4];
            a[2] = sA[r0 * LDA + kb + t4 + 4];
            a[3] = sA[(r0 + 8) * LDA + kb + t4 + 4];
            #pragma unroll
            for (int nf = 0; nf < 8; nf++) {
                unsigned b[2];
                int n = 128 + wc * 64 + nf * 8 + g;
                b[0] = sW[n * LDA + kb + t4];
                b[1] = sW[n * LDA + kb + t4 + 4];
                mma8(acc2[nf], a, b);
            }
        }

        #pragma unroll
        for (int nf = 0; nf < 8; nf++) {
            int col = wc * 64 + nf * 8 + t4 * 2;
            if (i0 < N) {
                float2 hv = *(const float2*)&h[(size_t)i0 * D + col];
                *(float2*)&out[(size_t)i0 * D + col] =
                    make_float2(hv.x + acc2[nf][0] + sc2[col], hv.y + acc2[nf][1] + sc2[col + 1]);
            }
            if (i1 < N) {
                float2 hv = *(const float2*)&h[(size_t)i1 * D + col];
                *(float2*)&out[(size_t)i1 * D + col] =
                    make_float2(hv.x + acc2[nf][2] + sc2[col], hv.y + acc2[nf][3] + sc2[col + 1]);
            }
        }
    }
}

// ---------------------------------------------------------------------------
extern "C" void kernel_launch(void* const* d_in, const int* in_sizes, int n_in,
                              void* d_out, int out_size)
{
    const float* h      = (const float*)d_in[0];
    const float* coords = (const float*)d_in[1];
    const void*  eraw   = (const void*)d_in[2];
    const float* W1     = (const float*)d_in[3];
    const float* b1     = (const float*)d_in[4];
    const float* W2     = (const float*)d_in[5];
    const float* b2     = (const float*)d_in[6];
    const float* U1     = (const float*)d_in[7];
    const float* c1     = (const float*)d_in[8];
    const float* U2     = (const float*)d_in[9];
    const float* c2     = (const float*)d_in[10];

    int N = in_sizes[0] / D;
    int E = in_sizes[2] / 2;
    if (N > MAXN) N = MAXN;

    const int SMEM1 = (384 * LDA + 32 * LDA) * 4;                // 219,648
    const int SMEM2 = (128 * LDA + 64 * LDA) * 4 + 3 * 128 * 4;  // 102,912
    const int SMEM3 = (256 * LDA + 128 * LDA) * 4 + 2 * 128 * 4; // 203,776

    cudaFuncSetAttribute(gemm1_kernel, cudaFuncAttributeMaxDynamicSharedMemorySize, SMEM1);
    cudaFuncSetAttribute(edge_kernel,  cudaFuncAttributeMaxDynamicSharedMemorySize, SMEM2);
    cudaFuncSetAttribute(node_kernel,  cudaFuncAttributeMaxDynamicSharedMemorySize, SMEM3);

    void* aggPtr = nullptr;
    cudaGetSymbolAddress(&aggPtr, g_agg);
    cudaMemsetAsync(aggPtr, 0, (size_t)N * D * sizeof(float));
    void* flagPtr = nullptr;
    cudaGetSymbolAddress(&flagPtr, g_oddor);
    cudaMemsetAsync(flagPtr, 0, sizeof(int));

    probe_kernel<<<1, 256>>>((const int*)eraw);
    gemm1_kernel<<<152, 512, SMEM1>>>(h, W1, U1, N);
    edge_kernel<<<296, 256, SMEM2>>>(coords, eraw, W1, b1, W2, b2, N, E);
    node_kernel<<<152, 512, SMEM3>>>(h, U1, U2, c1, c2, (float*)d_out, N);
}

// round 8
// speedup vs baseline: 1.6372x; 1.0897x over previous
#include <cuda_runtime.h>
#include <cstdint>
#include <cstdio>

#define D 128
#define MAXN 50000
#define LDA 132   // padded lead dim (floats) for conflict-free mma fragment loads

// Scratch (device globals: allocation-free contract). 16B-aligned for vector ld/st.
__device__ __align__(16) float g_PQR[(size_t)MAXN * 384];  // [N][384]: P=h@W1a^T, Q=h@W1b^T, R=h@U1a^T
__device__ __align__(16) float g_agg[(size_t)MAXN * D];    // scatter-add target
__device__ __align__(16) uint4 g_W2pack[16 * 4 * 2 * 32];  // [ks][wcc][nfpair][lane] -> 2 B-frags (coalesced)
__device__ int g_oddor;                                     // OR of odd 32-bit words of edge buffer

__device__ __forceinline__ unsigned f2tf(float x){
    unsigned u; asm("cvt.rna.tf32.f32 %0, %1;" : "=r"(u) : "f"(x)); return u;
}
__device__ __forceinline__ float silu(float x){           // exact-ish (2 MUFU)
    return x * (1.0f / (1.0f + __expf(-x)));
}
__device__ __forceinline__ float silu_fast(float x){      // 1 MUFU via hw tanh
    float hx = 0.5f * x;
    float t; asm("tanh.approx.f32 %0, %1;" : "=f"(t) : "f"(hx));
    return hx + hx * t;                                   // 0.5x(1+tanh(x/2))
}
__device__ __forceinline__ void mma8(float* c, const unsigned* a, const unsigned* b){
    asm volatile(
      "mma.sync.aligned.m16n8k8.row.col.f32.tf32.tf32.f32 "
      "{%0,%1,%2,%3},{%4,%5,%6,%7},{%8,%9},{%0,%1,%2,%3};\n"
      : "+f"(c[0]), "+f"(c[1]), "+f"(c[2]), "+f"(c[3])
      : "r"(a[0]), "r"(a[1]), "r"(a[2]), "r"(a[3]), "r"(b[0]), "r"(b[1]));
}
__device__ __forceinline__ void red2(float* addr, float x, float y){
    asm volatile("red.global.add.v2.f32 [%0], {%1,%2};" :: "l"(addr), "f"(x), "f"(y) : "memory");
}

// ---------------------------------------------------------------------------
// Probe: detect edge_index element width (int64 hi-words all zero vs int32).
// ---------------------------------------------------------------------------
__global__ void probe_kernel(const int* __restrict__ ebuf)
{
    int v = 0;
    for (int i = threadIdx.x; i < 4096; i += blockDim.x)
        v |= ebuf[2 * i + 1];
    if (v) atomicOr(&g_oddor, v);
}

// ---------------------------------------------------------------------------
// Pack W2 into warp-coalesced B-fragment entries:
// entry ((ks*4+wcc)*2+np)*32+lane holds, as 4 words:
//   w=0: b0 of nf=2np   w=1: b1 of nf=2np   w=2: b0 of nf=2np+1   w=3: b1 of nf=2np+1
// b-frag(wcc,nf,lane): row = wcc*32+nf*8+(lane>>2), col = ks*8+(lane&3)+r*4
// One warp LDG.128 at [entry*16 + lane*16] covers 512B contiguous.
// ---------------------------------------------------------------------------
__global__ void pack_kernel(const float* __restrict__ W2)
{
    int idx = blockIdx.x * 256 + threadIdx.x;   // word index
    if (idx >= 16 * 4 * 2 * 32 * 4) return;
    int wd   = idx & 3;
    int lane = (idx >> 2) & 31;
    int np   = (idx >> 7) & 1;
    int wcc  = (idx >> 8) & 3;
    int ks   = idx >> 10;
    int nf = np * 2 + (wd >> 1);
    int r  = wd & 1;
    int row = wcc * 32 + nf * 8 + (lane >> 2);
    int col = ks * 8 + (lane & 3) + r * 4;
    ((unsigned*)g_W2pack)[idx] = f2tf(W2[row * D + col]);
}

// ---------------------------------------------------------------------------
// Kernel 1: PQR = h @ Wcat^T. 512 threads, tile 32 rows x 384 cols.
// ---------------------------------------------------------------------------
__global__ __launch_bounds__(512) void gemm1_kernel(
    const float* __restrict__ h, const float* __restrict__ W1,
    const float* __restrict__ U1, int N)
{
    extern __shared__ unsigned sm[];
    unsigned* sW = sm;               // 384*LDA
    unsigned* sA = sm + 384 * LDA;   // 32*LDA
    int tid = threadIdx.x;

    for (int idx = tid; idx < 384 * D; idx += 512) {
        int r = idx >> 7, k = idx & 127;
        float v;
        if (r < 128)      v = W1[r * 257 + k];
        else if (r < 256) v = W1[(r - 128) * 257 + 128 + k];
        else              v = U1[(r - 256) * 256 + k];
        sW[r * LDA + k] = f2tf(v);
    }

    int w = tid >> 5, l = tid & 31, g = l >> 2, t4 = l & 3;
    int nbase = w * 24;
    int ntiles = (N + 31) >> 5;

    for (int tt = blockIdx.x; tt < ntiles; tt += gridDim.x) {
        __syncthreads();
        int row0 = tt << 5;
        #pragma unroll
        for (int it = 0; it < 2; ++it) {
            int idx = tid + it * 512;
            int r = idx >> 5, q = idx & 31;
            int i = row0 + r;
            float4 v = make_float4(0.f, 0.f, 0.f, 0.f);
            if (i < N) v = *(const float4*)&h[(size_t)i * D + q * 4];
            uint4 u = make_uint4(f2tf(v.x), f2tf(v.y), f2tf(v.z), f2tf(v.w));
            *(uint4*)&sA[r * LDA + q * 4] = u;
        }
        __syncthreads();

        float acc[2][3][4];
        #pragma unroll
        for (int mf = 0; mf < 2; mf++)
            #pragma unroll
            for (int nf = 0; nf < 3; nf++)
                #pragma unroll
                for (int q = 0; q < 4; q++) acc[mf][nf][q] = 0.f;

        #pragma unroll
        for (int ks = 0; ks < 16; ++ks) {
            int kb = ks * 8;
            unsigned a[2][4];
            #pragma unroll
            for (int mf = 0; mf < 2; mf++) {
                int r0 = mf * 16 + g;
                a[mf][0] = sA[r0 * LDA + kb + t4];
                a[mf][1] = sA[(r0 + 8) * LDA + kb + t4];
                a[mf][2] = sA[r0 * LDA + kb + t4 + 4];
                a[mf][3] = sA[(r0 + 8) * LDA + kb + t4 + 4];
            }
            #pragma unroll
            for (int nf = 0; nf < 3; nf++) {
                unsigned b[2];
                int n = nbase + nf * 8 + g;
                b[0] = sW[n * LDA + kb + t4];
                b[1] = sW[n * LDA + kb + t4 + 4];
                mma8(acc[0][nf], a[0], b);
                mma8(acc[1][nf], a[1], b);
            }
        }
        #pragma unroll
        for (int mf = 0; mf < 2; mf++) {
            int i0 = row0 + mf * 16 + g;
            int i1 = i0 + 8;
            #pragma unroll
            for (int nf = 0; nf < 3; nf++) {
                int col = nbase + nf * 8 + t4 * 2;
                if (i0 < N) *(float2*)&g_PQR[(size_t)i0 * 384 + col] = make_float2(acc[mf][nf][0], acc[mf][nf][1]);
                if (i1 < N) *(float2*)&g_PQR[(size_t)i1 * 384 + col] = make_float2(acc[mf][nf][2], acc[mf][nf][3]);
            }
        }
    }
}

// ---------------------------------------------------------------------------
// Kernel 2: edge kernel v4. Tile = 64 edges, 256 threads, 3 CTAs/SM.
// W2 B-fragments from L1-resident coalesced g_W2pack (512B/warp-load).
// Only sT (+biases) in smem: 35KB. 2 syncs/tile. Reg-direct scatter.
// ---------------------------------------------------------------------------
__global__ __launch_bounds__(256, 3) void edge_kernel(
    const float* __restrict__ coords, const void* __restrict__ eraw,
    const float* __restrict__ W1, const float* __restrict__ b1,
    const float* __restrict__ b2, int N, int E)
{
    extern __shared__ unsigned sm[];
    unsigned* sT  = sm;              // 64*LDA (t tile)
    float* sb1   = (float*)(sT + 64 * LDA);
    float* sb2   = sb1 + 128;
    float* swc   = sb2 + 128;
    int tid = threadIdx.x;

    const bool is64 = (g_oddor == 0);
    const int*       e32 = (const int*)eraw;
    const long long* e64 = (const long long*)eraw;

    if (tid < 128) { sb1[tid] = b1[tid]; sb2[tid] = b2[tid]; swc[tid] = W1[tid * 257 + 256]; }
    __syncthreads();

    int w = tid >> 5, l = tid & 31, g = l >> 2, t4 = l & 3;
    int wr = w & 1, wcc = w >> 1;     // 2 row-groups (32 rows) x 4 col-groups (32 cols)
    int ntiles = (E + 63) >> 6;

    for (int tt = blockIdx.x; tt < ntiles; tt += gridDim.x) {
        int e0 = tt << 6;

        // ---- build t tile: each warp covers edges w, w+8, ..., w+56 ----
        #pragma unroll
        for (int half = 0; half < 2; ++half) {
            float4 pv[4], qv[4]; float dv[4]; int el[4];
            #pragma unroll
            for (int it = 0; it < 4; ++it) {
                int e_loc = w + (half * 4 + it) * 8;
                el[it] = e_loc;
                int e = e0 + e_loc;
                int v = 0;
                if (l < 2 && e < E)
                    v = is64 ? (int)e64[(size_t)l * E + e] : e32[(size_t)l * E + e];
                int s = __shfl_sync(0xffffffffu, v, 0);
                int r = __shfl_sync(0xffffffffu, v, 1);
                if ((unsigned)s >= (unsigned)N) s = 0;
                if ((unsigned)r >= (unsigned)N) r = 0;
                float cd = 0.f;
                if (l < 3) cd = coords[s * 3 + l] - coords[r * 3 + l];
                float dx = __shfl_sync(0xffffffffu, cd, 0);
                float dy = __shfl_sync(0xffffffffu, cd, 1);
                float dz = __shfl_sync(0xffffffffu, cd, 2);
                dv[it] = sqrtf(dx * dx + dy * dy + dz * dz);
                pv[it] = *(const float4*)&g_PQR[(size_t)s * 384 + l * 4];
                qv[it] = *(const float4*)&g_PQR[(size_t)r * 384 + 128 + l * 4];
            }
            #pragma unroll
            for (int it = 0; it < 4; ++it) {
                int c = l * 4;
                float x0 = pv[it].x + qv[it].x + dv[it] * swc[c + 0] + sb1[c + 0];
                float x1 = pv[it].y + qv[it].y + dv[it] * swc[c + 1] + sb1[c + 1];
                float x2 = pv[it].z + qv[it].z + dv[it] * swc[c + 2] + sb1[c + 2];
                float x3 = pv[it].w + qv[it].w + dv[it] * swc[c + 3] + sb1[c + 3];
                uint4 st = make_uint4(f2tf(silu_fast(x0)), f2tf(silu_fast(x1)),
                                      f2tf(silu_fast(x2)), f2tf(silu_fast(x3)));
                *(uint4*)&sT[el[it] * LDA + c] = st;
            }
        }
        __syncthreads();

        // ---- GEMM2: warp computes 32 rows (wr) x 32 cols (wcc) ----
        float acc[2][4][4];
        #pragma unroll
        for (int mf = 0; mf < 2; mf++)
            #pragma unroll
            for (int nf = 0; nf < 4; nf++)
                #pragma unroll
                for (int q = 0; q < 4; q++) acc[mf][nf][q] = 0.f;

        #pragma unroll
        for (int ks = 0; ks < 16; ++ks) {
            int kb = ks * 8;
            unsigned a[2][4];
            #pragma unroll
            for (int mf = 0; mf < 2; mf++) {
                int r0 = wr * 32 + mf * 16 + g;
                a[mf][0] = sT[r0 * LDA + kb + t4];
                a[mf][1] = sT[(r0 + 8) * LDA + kb + t4];
                a[mf][2] = sT[r0 * LDA + kb + t4 + 4];
                a[mf][3] = sT[(r0 + 8) * LDA + kb + t4 + 4];
            }
            // 2 coalesced LDG.128 per ks: 512B contiguous per warp, L1-resident
            uint4 q0 = g_W2pack[((ks * 4 + wcc) * 2 + 0) * 32 + l];
            uint4 q1 = g_W2pack[((ks * 4 + wcc) * 2 + 1) * 32 + l];
            unsigned bb[8] = { q0.x, q0.y, q0.z, q0.w, q1.x, q1.y, q1.z, q1.w };
            #pragma unroll
            for (int nf = 0; nf < 4; nf++) {
                mma8(acc[0][nf], a[0], &bb[nf * 2]);
                mma8(acc[1][nf], a[1], &bb[nf * 2]);
            }
        }
        __syncthreads();   // sT free for next tile's t-build

        // ---- scatter straight from regs: bias + silu + red.v2 ----
        int rowlane = wr * 32 + l;     // this warp's 32 tile-rows
        int vrec = 0;
        if (e0 + rowlane < E)
            vrec = is64 ? (int)e64[(size_t)E + e0 + rowlane] : e32[(size_t)E + e0 + rowlane];
        if ((unsigned)vrec >= (unsigned)N) vrec = 0;

        #pragma unroll
        for (int mf = 0; mf < 2; mf++) {
            #pragma unroll
            for (int hh = 0; hh < 2; ++hh) {
                int rsel = mf * 16 + hh * 8 + g;
                int rec = __shfl_sync(0xffffffffu, vrec, rsel);
                bool valid = (e0 + wr * 32 + rsel) < E;
                if (valid) {
                    #pragma unroll
                    for (int nf = 0; nf < 4; nf++) {
                        int col = wcc * 32 + nf * 8 + t4 * 2;
                        float m0 = silu_fast(acc[mf][nf][hh * 2]     + sb2[col]);
                        float m1 = silu_fast(acc[mf][nf][hh * 2 + 1] + sb2[col + 1]);
                        red2(&g_agg[(size_t)rec * D + col], m0, m1);
                    }
                }
            }
        }
    }
}

// ---------------------------------------------------------------------------
// Kernel 3: node update. 512 threads, tile 128 nodes. Exact silu (protect accuracy).
// ---------------------------------------------------------------------------
__global__ __launch_bounds__(512) void node_kernel(
    const float* __restrict__ h, const float* __restrict__ U1,
    const float* __restrict__ U2, const float* __restrict__ c1,
    const float* __restrict__ c2, float* __restrict__ out, int N)
{
    extern __shared__ unsigned sm[];
    unsigned* sW = sm;               // 256*LDA (U1b rows 0..127, U2 rows 128..255)
    unsigned* sA = sm + 256 * LDA;   // 128*LDA (agg tile, then t tile)
    float* sc1 = (float*)(sA + 128 * LDA);
    float* sc2 = sc1 + 128;
    int tid = threadIdx.x;

    #pragma unroll
    for (int it = 0; it < 16; ++it) {
        int idx = tid + it * 512;
        int r = idx >> 5, q = idx & 31;
        float4 v;
        if (r < 128) v = *(const float4*)&U1[r * 256 + 128 + q * 4];
        else         v = *(const float4*)&U2[(r - 128) * D + q * 4];
        uint4 u = make_uint4(f2tf(v.x), f2tf(v.y), f2tf(v.z), f2tf(v.w));
        *(uint4*)&sW[r * LDA + q * 4] = u;
    }
    if (tid < 128) { sc1[tid] = c1[tid]; sc2[tid] = c2[tid]; }

    int w = tid >> 5, l = tid & 31, g = l >> 2, t4 = l & 3;
    int wr = w >> 1, wc = w & 1;
    int ntiles = (N + 127) >> 7;

    for (int tt = blockIdx.x; tt < ntiles; tt += gridDim.x) {
        __syncthreads();
        int n0 = tt << 7;
        #pragma unroll
        for (int it = 0; it < 8; ++it) {
            int idx = tid + it * 512;
            int r = idx >> 5, q = idx & 31;
            int i = n0 + r;
            float4 v = make_float4(0.f, 0.f, 0.f, 0.f);
            if (i < N) v = *(const float4*)&g_agg[(size_t)i * D + q * 4];
            uint4 u = make_uint4(f2tf(v.x), f2tf(v.y), f2tf(v.z), f2tf(v.w));
            *(uint4*)&sA[r * LDA + q * 4] = u;
        }
        __syncthreads();

        float acc[8][4];
        #pragma unroll
        for (int nf = 0; nf < 8; nf++)
            #pragma unroll
            for (int q = 0; q < 4; q++) acc[nf][q] = 0.f;

        #pragma unroll
        for (int ks = 0; ks < 16; ++ks) {
            int kb = ks * 8;
            unsigned a[4];
            int r0 = wr * 16 + g;
            a[0] = sA[r0 * LDA + kb + t4];
            a[1] = sA[(r0 + 8) * LDA + kb + t4];
            a[2] = sA[r0 * LDA + kb + t4 + 4];
            a[3] = sA[(r0 + 8) * LDA + kb + t4 + 4];
            #pragma unroll
            for (int nf = 0; nf < 8; nf++) {
                unsigned b[2];
                int n = wc * 64 + nf * 8 + g;
                b[0] = sW[n * LDA + kb + t4];
                b[1] = sW[n * LDA + kb + t4 + 4];
                mma8(acc[nf], a, b);
            }
        }
        __syncthreads();  // all warps done reading agg tile before overwrite with t

        int rA = wr * 16 + g;
        int i0 = n0 + rA, i1 = i0 + 8;
        #pragma unroll
        for (int nf = 0; nf < 8; nf++) {
            int col = wc * 64 + nf * 8 + t4 * 2;
            float r00 = 0.f, r01 = 0.f, r10 = 0.f, r11 = 0.f;
            if (i0 < N) { float2 rv = *(const float2*)&g_PQR[(size_t)i0 * 384 + 256 + col]; r00 = rv.x; r01 = rv.y; }
            if (i1 < N) { float2 rv = *(const float2*)&g_PQR[(size_t)i1 * 384 + 256 + col]; r10 = rv.x; r11 = rv.y; }
            sA[rA * LDA + col]           = f2tf(silu(acc[nf][0] + r00 + sc1[col]));
            sA[rA * LDA + col + 1]       = f2tf(silu(acc[nf][1] + r01 + sc1[col + 1]));
            sA[(rA + 8) * LDA + col]     = f2tf(silu(acc[nf][2] + r10 + sc1[col]));
            sA[(rA + 8) * LDA + col + 1] = f2tf(silu(acc[nf][3] + r11 + sc1[col + 1]));
        }
        __syncthreads();

        float acc2[8][4];
        #pragma unroll
        for (int nf = 0; nf < 8; nf++)
            #pragma unroll
            for (int q = 0; q < 4; q++) acc2[nf][q] = 0.f;

        #pragma unroll
        for (int ks = 0; ks < 16; ++ks) {
            int kb = ks * 8;
            unsigned a[4];
            int r0 = wr * 16 + g;
            a[0] = sA[r0 * LDA + kb + t4];
            a[1] = sA[(r0 + 8) * LDA + kb + t4];
            a[2] = sA[r0 * LDA + kb + t4 + 4];
            a[3] = sA[(r0 + 8) * LDA + kb + t4 + 4];
            #pragma unroll
            for (int nf = 0; nf < 8; nf++) {
                unsigned b[2];
                int n = 128 + wc * 64 + nf * 8 + g;
                b[0] = sW[n * LDA + kb + t4];
                b[1] = sW[n * LDA + kb + t4 + 4];
                mma8(acc2[nf], a, b);
            }
        }

        #pragma unroll
        for (int nf = 0; nf < 8; nf++) {
            int col = wc * 64 + nf * 8 + t4 * 2;
            if (i0 < N) {
                float2 hv = *(const float2*)&h[(size_t)i0 * D + col];
                *(float2*)&out[(size_t)i0 * D + col] =
                    make_float2(hv.x + acc2[nf][0] + sc2[col], hv.y + acc2[nf][1] + sc2[col + 1]);
            }
            if (i1 < N) {
                float2 hv = *(const float2*)&h[(size_t)i1 * D + col];
                *(float2*)&out[(size_t)i1 * D + col] =
                    make_float2(hv.x + acc2[nf][2] + sc2[col], hv.y + acc2[nf][3] + sc2[col + 1]);
            }
        }
    }
}

// ---------------------------------------------------------------------------
extern "C" void kernel_launch(void* const* d_in, const int* in_sizes, int n_in,
                              void* d_out, int out_size)
{
    const float* h      = (const float*)d_in[0];
    const float* coords = (const float*)d_in[1];
    const void*  eraw   = (const void*)d_in[2];
    const float* W1     = (const float*)d_in[3];
    const float* b1     = (const float*)d_in[4];
    const float* W2     = (const float*)d_in[5];
    const float* b2     = (const float*)d_in[6];
    const float* U1     = (const float*)d_in[7];
    const float* c1     = (const float*)d_in[8];
    const float* U2     = (const float*)d_in[9];
    const float* c2     = (const float*)d_in[10];

    int N = in_sizes[0] / D;
    int E = in_sizes[2] / 2;
    if (N > MAXN) N = MAXN;

    const int SMEM1 = (384 * LDA + 32 * LDA) * 4;                // 219,648
    const int SMEM2 = 64 * LDA * 4 + 3 * 128 * 4;                // 35,328
    const int SMEM3 = (256 * LDA + 128 * LDA) * 4 + 2 * 128 * 4; // 203,776

    cudaFuncSetAttribute(gemm1_kernel, cudaFuncAttributeMaxDynamicSharedMemorySize, SMEM1);
    cudaFuncSetAttribute(edge_kernel,  cudaFuncAttributeMaxDynamicSharedMemorySize, SMEM2);
    cudaFuncSetAttribute(node_kernel,  cudaFuncAttributeMaxDynamicSharedMemorySize, SMEM3);

    void* aggPtr = nullptr;
    cudaGetSymbolAddress(&aggPtr, g_agg);
    cudaMemsetAsync(aggPtr, 0, (size_t)N * D * sizeof(float));
    void* flagPtr = nullptr;
    cudaGetSymbolAddress(&flagPtr, g_oddor);
    cudaMemsetAsync(flagPtr, 0, sizeof(int));

    probe_kernel<<<1, 256>>>((const int*)eraw);
    pack_kernel<<<64, 256>>>(W2);
    gemm1_kernel<<<152, 512, SMEM1>>>(h, W1, U1, N);
    edge_kernel<<<444, 256, SMEM2>>>(coords, eraw, W1, b1, b2, N, E);
    node_kernel<<<152, 512, SMEM3>>>(h, U1, U2, c1, c2, (float*)d_out, N);
}